// round 7
// baseline (speedup 1.0000x reference)
#include <cuda_runtime.h>
#include <cstdint>

#define BATCH 256
#define DLAT  32
#define HID   512
#define GENES 4000
#define NCH   8
#define GC    500      // genes per chunk; 500 = 4*125 -> tg<125 owns 4 genes
#define GT    512      // U rows per block (rows 500..511 written as zeros)
#define NT    256
#define PANEL 2052     // floats per A-panel: 512*4 + 4 skew (8208 B, 16B-aligned)

// Deterministic partial-Gram buffer: [chunk][batch][32*32]
__device__ float g_gramPart[(size_t)NCH * BATCH * DLAT * DLAT];
__device__ float g_lossb[BATCH];

#define FMA2(accv, av, bv) \
    asm("fma.rn.f32x2 %0, %1, %2, %0;" : "+l"(accv) : "l"(av), "l"(bv))
#define SPLAT2(dst, s) \
    asm("mov.b64 %0, {%1,%1};" : "=l"(dst) : "r"(__float_as_uint(s)))
#define PACK2(dst, lo, hi) \
    asm("mov.b64 %0, {%1,%2};" : "=l"(dst) : "r"(__float_as_uint(lo)), "r"(__float_as_uint(hi)))

// ---------------------------------------------------------------------------
// Main kernel: one block = (batch b, gene chunk ch).
//   Phase 0: pre1/mask; masked W1 stored as 8 skewed PANELS [k][4 floats].
//   Phase 1: thread (th = i-half, tg = 4 consecutive genes) computes
//            V[16 i x 4 g] with f32x2 FMA. W2 rows are DOUBLE-BUFFERED in
//            registers at 4-k granularity so the LDG latency is hidden.
//   Epilogue: U = sqrt(c)*V written row-major [512][32] over the same buffer.
//   Phase 2: 32x32 SYRK with f32x2.
// ---------------------------------------------------------------------------
__global__ void __launch_bounds__(NT, 2)
pullback_main(const float* __restrict__ z,  const float* __restrict__ W1,
              const float* __restrict__ b1, const float* __restrict__ W2,
              const float* __restrict__ b2, const float* __restrict__ lth)
{
    extern __shared__ float smem[];
    float* sW1m = smem;                  // 8 panels * PANEL floats
    float* sU   = smem;                  // [512][32] U tile (reuse)
    float* sH   = smem + 8 * PANEL;      // [512] relu(pre1)
    float* sZ   = sH + HID;              // [32]

    const int tid = threadIdx.x;
    const int b   = blockIdx.x;
    const int ch  = blockIdx.y;
    const int g0  = ch * GC;

    if (tid < DLAT) sZ[tid] = z[b * DLAT + tid];
    __syncthreads();

    // ---- Phase 0: pre1 / mask / masked W1 into panels ----
    for (int jk = 0; jk < HID / NT; ++jk) {
        const int k = tid + jk * NT;
        float wv[DLAT];
        float pre = b1[k];
        #pragma unroll
        for (int i = 0; i < DLAT; ++i) {
            wv[i] = W1[i * HID + k];          // coalesced across tid
            pre = fmaf(sZ[i], wv[i], pre);
        }
        const bool act = pre > 0.0f;
        sH[k] = act ? pre : 0.0f;
        #pragma unroll
        for (int q = 0; q < 8; ++q) {
            float4 v;
            v.x = act ? wv[4*q+0] : 0.0f;
            v.y = act ? wv[4*q+1] : 0.0f;
            v.z = act ? wv[4*q+2] : 0.0f;
            v.w = act ? wv[4*q+3] : 0.0f;
            *reinterpret_cast<float4*>(sW1m + q * PANEL + k * 4) = v;
        }
    }
    __syncthreads();

    // ---- Phase 1: 16 i (one half) x 4 consecutive genes per thread ----
    const int  th = tid & 1;               // i-half: cols th*16 .. th*16+15
    const int  tg = tid >> 1;              // gene group
    const bool gv = (tg < GC / 4);         // 125 active groups
    const int  gp = g0 + (gv ? 4 * tg : 0);

    // acc[j*8 + e]: gene j (0..3), i-pair e (0..7) within this thread's half
    unsigned long long acc[32];
    #pragma unroll
    for (int p = 0; p < 32; ++p) acc[p] = 0ULL;
    unsigned long long pr01 = 0ULL, pr23 = 0ULL;   // packed pre2 accumulators

    const float* rowp = sW1m + th * (4 * PANEL);
    const float* sHp  = sH;
    const float* w2k  = W2 + gp;

    // Preload W2 group 0 (k = 0..3)
    float4 wcur[4];
    #pragma unroll
    for (int kk = 0; kk < 4; ++kk)
        wcur[kk] = *reinterpret_cast<const float4*>(w2k + kk * GENES);
    w2k += 4 * GENES;

    #pragma unroll 2
    for (int k4 = 0; k4 < HID / 4; ++k4) {
        // Prefetch NEXT 4-k group (clamped re-read of the last valid group
        // on the final iteration; values never used).
        const float* wnp = (k4 < HID / 4 - 1) ? w2k : (w2k - 4 * GENES);
        float4 wnxt[4];
        #pragma unroll
        for (int kk = 0; kk < 4; ++kk)
            wnxt[kk] = *reinterpret_cast<const float4*>(wnp + kk * GENES);
        w2k += 4 * GENES;

        const float4 hv = *reinterpret_cast<const float4*>(sHp);  // LDS.128
        const float hks[4] = {hv.x, hv.y, hv.z, hv.w};

        #pragma unroll
        for (int kk = 0; kk < 4; ++kk) {
            const float4 w2v = wcur[kk];
            unsigned long long a0, a1, a2, a3, hkp, w01, w23;
            SPLAT2(a0, w2v.x);
            SPLAT2(a1, w2v.y);
            SPLAT2(a2, w2v.z);
            SPLAT2(a3, w2v.w);
            SPLAT2(hkp, hks[kk]);
            PACK2(w01, w2v.x, w2v.y);
            PACK2(w23, w2v.z, w2v.w);
            FMA2(pr01, hkp, w01);
            FMA2(pr23, hkp, w23);

            #pragma unroll
            for (int q = 0; q < 4; ++q) {
                const ulonglong2 t = *reinterpret_cast<const ulonglong2*>(
                    rowp + q * PANEL + kk * 4);     // immediate offsets
                FMA2(acc[0*8 + 2*q],     t.x, a0);
                FMA2(acc[0*8 + 2*q + 1], t.y, a0);
                FMA2(acc[1*8 + 2*q],     t.x, a1);
                FMA2(acc[1*8 + 2*q + 1], t.y, a1);
                FMA2(acc[2*8 + 2*q],     t.x, a2);
                FMA2(acc[2*8 + 2*q + 1], t.y, a2);
                FMA2(acc[3*8 + 2*q],     t.x, a3);
                FMA2(acc[3*8 + 2*q + 1], t.y, a3);
            }
        }

        #pragma unroll
        for (int kk = 0; kk < 4; ++kk) wcur[kk] = wnxt[kk];
        rowp += 16;          // 4 k * 4 floats
        sHp  += 4;
    }

    // All warps must finish READING the panels before overwriting with U.
    __syncthreads();

    // ---- Epilogue: per-gene weight, U = sqrt(c)*V, row-major [512][32] ----
    float pr2f[4];
    {
        unsigned int l, h;
        asm("mov.b64 {%0,%1}, %2;" : "=r"(l), "=r"(h) : "l"(pr01));
        pr2f[0] = __uint_as_float(l); pr2f[1] = __uint_as_float(h);
        asm("mov.b64 {%0,%1}, %2;" : "=r"(l), "=r"(h) : "l"(pr23));
        pr2f[2] = __uint_as_float(l); pr2f[3] = __uint_as_float(h);
    }
    #pragma unroll
    for (int j = 0; j < 4; ++j) {
        const int row = 4 * tg + j;            // rows 500..511 get sc=0 zeros
        float sc = 0.0f;
        if (gv) {
            const int g = gp + j;
            const float x  = pr2f[j] + b2[g];
            const float mu = (x > 0.f) ? (x + log1pf(__expf(-x)))
                                       : log1pf(__expf(x));
            const float sg = 1.0f / (1.0f + __expf(-x));
            const float thv = __expf(lth[g]);
            const float wt = thv / fmaf(mu, mu + thv, 1e-6f);
            sc = sg * sqrtf(wt);
        }
        float* urow = sU + row * DLAT + th * 16;
        #pragma unroll
        for (int q = 0; q < 4; ++q) {
            unsigned int l0, h0, l1, h1;
            asm("mov.b64 {%0,%1}, %2;" : "=r"(l0), "=r"(h0) : "l"(acc[j*8 + 2*q]));
            asm("mov.b64 {%0,%1}, %2;" : "=r"(l1), "=r"(h1) : "l"(acc[j*8 + 2*q + 1]));
            float4 v;
            v.x = sc * __uint_as_float(l0);
            v.y = sc * __uint_as_float(h0);
            v.z = sc * __uint_as_float(l1);
            v.w = sc * __uint_as_float(h1);
            *reinterpret_cast<float4*>(urow + (q << 2)) = v;
        }
    }
    __syncthreads();

    // ---- Phase 2: Gram partial = U U^T, f32x2, 2x2 tile per thread ----
    const int ti = tid & 15;        // i0 = 2*ti
    const int tj = tid >> 4;        // j0 = 2*tj
    const float* pa = sU + 2 * ti;
    const float* pb = sU + 2 * tj;
    unsigned long long ga0 = 0ULL, ga1 = 0ULL;  // rows i0, i0+1 x cols {j0,j0+1}

    #pragma unroll 1
    for (int g8 = 0; g8 < GT / 8; ++g8) {
        #pragma unroll
        for (int s = 0; s < 8; ++s) {
            const unsigned long long avu =
                *reinterpret_cast<const unsigned long long*>(pa + s * DLAT);
            const unsigned long long bvu =
                *reinterpret_cast<const unsigned long long*>(pb + s * DLAT);
            unsigned int alo, ahi;
            asm("mov.b64 {%0,%1}, %2;" : "=r"(alo), "=r"(ahi) : "l"(avu));
            unsigned long long ad0, ad1;
            asm("mov.b64 %0, {%1,%1};" : "=l"(ad0) : "r"(alo));
            asm("mov.b64 %0, {%1,%1};" : "=l"(ad1) : "r"(ahi));
            FMA2(ga0, ad0, bvu);
            FMA2(ga1, ad1, bvu);
        }
        pa += 8 * DLAT;
        pb += 8 * DLAT;
    }

    float* dst = g_gramPart + ((size_t)ch * BATCH + b) * (DLAT * DLAT);
    {
        unsigned int l0, h0, l1, h1;
        asm("mov.b64 {%0,%1}, %2;" : "=r"(l0), "=r"(h0) : "l"(ga0));
        asm("mov.b64 {%0,%1}, %2;" : "=r"(l1), "=r"(h1) : "l"(ga1));
        dst[(2*ti    ) * DLAT + 2*tj    ] = __uint_as_float(l0);
        dst[(2*ti    ) * DLAT + 2*tj + 1] = __uint_as_float(h0);
        dst[(2*ti + 1) * DLAT + 2*tj    ] = __uint_as_float(l1);
        dst[(2*ti + 1) * DLAT + 2*tj + 1] = __uint_as_float(h1);
    }
}

// ---------------------------------------------------------------------------
// Per-batch loss: sum_ij (sum_ch Gram_partial - I)^2  (deterministic)
// ---------------------------------------------------------------------------
__global__ void __launch_bounds__(256)
loss_per_b_kernel()
{
    const int b = blockIdx.x;
    const int t = threadIdx.x;
    float accl = 0.0f;
    #pragma unroll
    for (int r = 0; r < 4; ++r) {
        const int ij = t + r * 256;
        float s = 0.0f;
        #pragma unroll
        for (int c = 0; c < NCH; ++c)
            s += g_gramPart[((size_t)c * BATCH + b) * 1024 + ij];
        if (ij % 33 == 0) s -= 1.0f;   // ALPHA * I on the diagonal
        accl = fmaf(s, s, accl);
    }
    __shared__ float red[256];
    red[t] = accl;
    __syncthreads();
    for (int o = 128; o > 0; o >>= 1) {
        if (t < o) red[t] += red[t + o];
        __syncthreads();
    }
    if (t == 0) g_lossb[b] = red[0];
}

__global__ void __launch_bounds__(256)
final_reduce_kernel(float* __restrict__ out)
{
    const int t = threadIdx.x;
    __shared__ float red[256];
    red[t] = g_lossb[t];
    __syncthreads();
    for (int o = 128; o > 0; o >>= 1) {
        if (t < o) red[t] += red[t + o];
        __syncthreads();
    }
    if (t == 0) out[0] = red[0] * (1.0f / (float)BATCH);
}

// ---------------------------------------------------------------------------
extern "C" void kernel_launch(void* const* d_in, const int* in_sizes, int n_in,
                              void* d_out, int out_size)
{
    const float* z   = (const float*)d_in[0];
    const float* W1  = (const float*)d_in[1];
    const float* b1  = (const float*)d_in[2];
    const float* W2  = (const float*)d_in[3];
    const float* b2  = (const float*)d_in[4];
    const float* lth = (const float*)d_in[5];

    const size_t smem_bytes =
        (size_t)(8 * PANEL + HID + DLAT) * sizeof(float);  // 67,840 B
    cudaFuncSetAttribute(pullback_main,
                         cudaFuncAttributeMaxDynamicSharedMemorySize,
                         (int)smem_bytes);

    dim3 grid(BATCH, NCH);
    pullback_main<<<grid, NT, smem_bytes>>>(z, W1, b1, W2, b2, lth);
    loss_per_b_kernel<<<BATCH, 256>>>();
    final_reduce_kernel<<<1, 256>>>((float*)d_out);
}

// round 9
// speedup vs baseline: 1.6547x; 1.6547x over previous
#include <cuda_runtime.h>
#include <cstdint>

#define BATCH 256
#define DLAT  32
#define HID   512
#define GENES 4000
#define NTIL  16        // gene tiles of 256 (4096 padded)
#define USTR  34

__device__ uint4 g_A[2 * 256 * 32 * 32];        // [prec][gtile16][ks][lane]{a0..a3}
__device__ uint2 g_B[2 * 256 * 32 * 5 * 32];    // [prec][b][ks][nt][lane]{b0,b1}
__device__ float g_pre1[BATCH * HID];
__device__ float g_gramPart[(size_t)NTIL * BATCH * DLAT * DLAT];
__device__ float g_lossb[BATCH];

#define FMA2(a, x, y) asm("fma.rn.f32x2 %0, %1, %2, %0;" : "+l"(a) : "l"(x), "l"(y))
#define MMA(d, a, b) \
    asm volatile("mma.sync.aligned.m16n8k16.row.col.f32.bf16.bf16.f32 " \
        "{%0,%1,%2,%3}, {%4,%5,%6,%7}, {%8,%9}, {%0,%1,%2,%3};" \
        : "+f"((d)[0]), "+f"((d)[1]), "+f"((d)[2]), "+f"((d)[3]) \
        : "r"((a).x), "r"((a).y), "r"((a).z), "r"((a).w), "r"((b).x), "r"((b).y))

__device__ __forceinline__ unsigned f2bf(float f) {
    unsigned u = __float_as_uint(f);
    return (u + 0x7FFFu + ((u >> 16) & 1u)) >> 16;
}
__device__ __forceinline__ float bf2f(unsigned h) { return __uint_as_float(h << 16); }
__device__ __forceinline__ unsigned packbf(float a, float b, unsigned& lo) {
    const unsigned ha = f2bf(a), hb = f2bf(b);
    lo = f2bf(a - bf2f(ha)) | (f2bf(b - bf2f(hb)) << 16);
    return ha | (hb << 16);
}

// ---- prep: pre1[b][k] ----
__global__ void __launch_bounds__(256)
pre1_kernel(const float* __restrict__ z, const float* __restrict__ W1,
            const float* __restrict__ b1)
{
    __shared__ float sZ[DLAT];
    const int b = blockIdx.x, tid = threadIdx.x;
    if (tid < DLAT) sZ[tid] = z[b * DLAT + tid];
    __syncthreads();
    #pragma unroll
    for (int kk = 0; kk < 2; ++kk) {
        const int k = tid + kk * 256;
        float acc = b1[k];
        #pragma unroll
        for (int i = 0; i < DLAT; ++i) acc = fmaf(sZ[i], W1[i * HID + k], acc);
        g_pre1[b * HID + k] = acc;
    }
}

// ---- prep: A fragments from W2 (per 16-gene tile) ----
__global__ void __launch_bounds__(256)
prepA_kernel(const float* __restrict__ W2)
{
    __shared__ float sW2[HID * 16];          // [k][g-local]
    const int gt = blockIdx.x, tid = threadIdx.x;
    for (int idx = tid; idx < HID * 16; idx += 256) {
        const int k = idx >> 4, gl = idx & 15, g = gt * 16 + gl;
        sW2[idx] = (g < GENES) ? W2[k * GENES + g] : 0.0f;
    }
    __syncthreads();
    const int lane = tid & 31, ks8 = tid >> 5;
    const int r = lane >> 2, c = lane & 3;
    #pragma unroll
    for (int ko = 0; ko < 4; ++ko) {
        const int ks = ko * 8 + ks8, k0 = ks * 16 + 2 * c;
        uint4 hi, lo;
        hi.x = packbf(sW2[k0 * 16 + r],       sW2[(k0 + 1) * 16 + r],       lo.x);
        hi.y = packbf(sW2[k0 * 16 + r + 8],   sW2[(k0 + 1) * 16 + r + 8],   lo.y);
        hi.z = packbf(sW2[(k0 + 8) * 16 + r],     sW2[(k0 + 9) * 16 + r],     lo.z);
        hi.w = packbf(sW2[(k0 + 8) * 16 + r + 8], sW2[(k0 + 9) * 16 + r + 8], lo.w);
        g_A[(0 * 256 + gt) * 1024 + ks * 32 + lane] = hi;
        g_A[(1 * 256 + gt) * 1024 + ks * 32 + lane] = lo;
    }
}

// ---- prep: B fragments = (masked W1 | h) per batch ----
__global__ void __launch_bounds__(256)
prepB_kernel(const float* __restrict__ W1)
{
    extern __shared__ float sm[];
    float* sW1 = sm;                // [32][512]
    float* sP  = sm + DLAT * HID;   // [512] pre1
    const int b = blockIdx.x, tid = threadIdx.x;
    for (int idx = tid; idx < DLAT * HID; idx += 256) sW1[idx] = W1[idx];
    for (int idx = tid; idx < HID; idx += 256) sP[idx] = g_pre1[b * HID + idx];
    __syncthreads();
    const int lane = tid & 31, ks8 = tid >> 5;
    const int r = lane >> 2, c = lane & 3;
    #pragma unroll
    for (int ko = 0; ko < 4; ++ko) {
        const int ks = ko * 8 + ks8, k0 = ks * 16 + 2 * c;
        const bool m0 = sP[k0] > 0.f, m1 = sP[k0 + 1] > 0.f;
        const bool m8 = sP[k0 + 8] > 0.f, m9 = sP[k0 + 9] > 0.f;
        #pragma unroll
        for (int nt = 0; nt < 5; ++nt) {
            float v0 = 0.f, v1 = 0.f, v8 = 0.f, v9 = 0.f;
            if (nt < 4) {
                const int n = nt * 8 + r;
                v0 = m0 ? sW1[n * HID + k0]     : 0.f;
                v1 = m1 ? sW1[n * HID + k0 + 1] : 0.f;
                v8 = m8 ? sW1[n * HID + k0 + 8] : 0.f;
                v9 = m9 ? sW1[n * HID + k0 + 9] : 0.f;
            } else if (r == 0) {                 // n = 32: h row
                v0 = fmaxf(sP[k0], 0.f);     v1 = fmaxf(sP[k0 + 1], 0.f);
                v8 = fmaxf(sP[k0 + 8], 0.f); v9 = fmaxf(sP[k0 + 9], 0.f);
            }
            uint2 hi, lo;
            hi.x = packbf(v0, v1, lo.x);
            hi.y = packbf(v8, v9, lo.y);
            const int base = ks * 160 + nt * 32 + lane;
            g_B[(0 * 256 + b) * 5120 + base] = hi;
            g_B[(1 * 256 + b) * 5120 + base] = lo;
        }
    }
}

__device__ __forceinline__ float gene_scale(float pre2, int g,
                                            const float* b2, const float* lth)
{
    if (g >= GENES) return 0.0f;
    const float x  = pre2 + __ldg(b2 + g);
    const float mu = (x > 0.f) ? (x + log1pf(__expf(-x))) : log1pf(__expf(x));
    const float sg = 1.0f / (1.0f + __expf(-x));
    const float th = __expf(__ldg(lth + g));
    return sg * sqrtf(th / fmaf(mu, mu + th, 1e-6f));
}

// ---- main: warp-level bf16 MMA (3-term) + epilogue + SYRK ----
__global__ void __launch_bounds__(256, 1)
mma_main(const float* __restrict__ b2, const float* __restrict__ lth)
{
    extern __shared__ float sU[];   // [2 b][256 g][USTR]
    const int tid = threadIdx.x, w = tid >> 5, lane = tid & 31;
    const int tile = blockIdx.x, bg = blockIdx.y;

    const uint4* pA[2][2];
    #pragma unroll
    for (int p = 0; p < 2; ++p)
        #pragma unroll
        for (int m = 0; m < 2; ++m)
            pA[p][m] = g_A + (p * 256 + tile * 16 + w * 2 + m) * 1024 + lane;
    const uint2* pB[2][2];
    #pragma unroll
    for (int p = 0; p < 2; ++p)
        #pragma unroll
        for (int bb = 0; bb < 2; ++bb)
            pB[p][bb] = g_B + (p * 256 + bg * 2 + bb) * 5120 + lane;

    float acc[2][2][5][4];
    #pragma unroll
    for (int bb = 0; bb < 2; ++bb)
        #pragma unroll
        for (int m = 0; m < 2; ++m)
            #pragma unroll
            for (int n = 0; n < 5; ++n)
                #pragma unroll
                for (int e = 0; e < 4; ++e) acc[bb][m][n][e] = 0.0f;

    uint4 Ab[2][2][2];
    uint2 Bb[2][2][2][5];
    #pragma unroll
    for (int p = 0; p < 2; ++p) {
        #pragma unroll
        for (int m = 0; m < 2; ++m) Ab[0][p][m] = pA[p][m][0];
        #pragma unroll
        for (int bb = 0; bb < 2; ++bb)
            #pragma unroll
            for (int n = 0; n < 5; ++n) Bb[0][p][bb][n] = pB[p][bb][n * 32];
    }

    #pragma unroll 2
    for (int ks = 0; ks < 32; ++ks) {
        const int cur = ks & 1, nxt = cur ^ 1;
        const int ksn = (ks < 31) ? ks + 1 : 31;
        #pragma unroll
        for (int p = 0; p < 2; ++p) {
            #pragma unroll
            for (int m = 0; m < 2; ++m) Ab[nxt][p][m] = pA[p][m][ksn * 32];
            #pragma unroll
            for (int bb = 0; bb < 2; ++bb)
                #pragma unroll
                for (int n = 0; n < 5; ++n)
                    Bb[nxt][p][bb][n] = pB[p][bb][ksn * 160 + n * 32];
        }
        #pragma unroll
        for (int bb = 0; bb < 2; ++bb)
            #pragma unroll
            for (int n = 0; n < 5; ++n)
                #pragma unroll
                for (int m = 0; m < 2; ++m) {
                    MMA(acc[bb][m][n], Ab[cur][0][m], Bb[cur][0][bb][n]);
                    MMA(acc[bb][m][n], Ab[cur][0][m], Bb[cur][1][bb][n]);
                    MMA(acc[bb][m][n], Ab[cur][1][m], Bb[cur][0][bb][n]);
                }
    }

    // epilogue: pre2 from col 32 (nt=4, in-tile col 0) -> sc -> U in smem
    const int r = lane >> 2, c2 = (lane & 3) * 2;
    #pragma unroll
    for (int bb = 0; bb < 2; ++bb)
        #pragma unroll
        for (int m = 0; m < 2; ++m) {
            const float pr  = __shfl_sync(0xFFFFFFFFu, acc[bb][m][4][0], lane & 28);
            const float pr8 = __shfl_sync(0xFFFFFFFFu, acc[bb][m][4][2], lane & 28);
            const int gbase = tile * 256 + w * 32 + m * 16;
            const float sc0 = gene_scale(pr,  gbase + r,     b2, lth);
            const float sc1 = gene_scale(pr8, gbase + r + 8, b2, lth);
            float* u0 = sU + (bb * 256 + w * 32 + m * 16 + r) * USTR;
            float* u1 = u0 + 8 * USTR;
            #pragma unroll
            for (int n = 0; n < 4; ++n) {
                *reinterpret_cast<float2*>(u0 + n * 8 + c2) =
                    make_float2(acc[bb][m][n][0] * sc0, acc[bb][m][n][1] * sc0);
                *reinterpret_cast<float2*>(u1 + n * 8 + c2) =
                    make_float2(acc[bb][m][n][2] * sc1, acc[bb][m][n][3] * sc1);
            }
        }
    __syncthreads();

    // SYRK: Gram_b = U^T U (f32x2, 2x2 per thread)
    const int ti = tid & 15, tj = tid >> 4;
    #pragma unroll 1
    for (int bb = 0; bb < 2; ++bb) {
        const float* ub = sU + bb * 256 * USTR;
        const float* pa = ub + 2 * ti;
        const float* pq = ub + 2 * tj;
        unsigned long long ga0 = 0ULL, ga1 = 0ULL;
        #pragma unroll 4
        for (int rI = 0; rI < 256; ++rI) {
            const unsigned long long av =
                *reinterpret_cast<const unsigned long long*>(pa + rI * USTR);
            const unsigned long long bv =
                *reinterpret_cast<const unsigned long long*>(pq + rI * USTR);
            unsigned alo, ahi;
            asm("mov.b64 {%0,%1}, %2;" : "=r"(alo), "=r"(ahi) : "l"(av));
            unsigned long long ad0, ad1;
            asm("mov.b64 %0, {%1,%1};" : "=l"(ad0) : "r"(alo));
            asm("mov.b64 %0, {%1,%1};" : "=l"(ad1) : "r"(ahi));
            FMA2(ga0, ad0, bv);
            FMA2(ga1, ad1, bv);
        }
        float* dst = g_gramPart + ((size_t)tile * BATCH + bg * 2 + bb) * 1024;
        unsigned l0, h0, l1, h1;
        asm("mov.b64 {%0,%1}, %2;" : "=r"(l0), "=r"(h0) : "l"(ga0));
        asm("mov.b64 {%0,%1}, %2;" : "=r"(l1), "=r"(h1) : "l"(ga1));
        dst[(2*ti)   * 32 + 2*tj    ] = __uint_as_float(l0);
        dst[(2*ti)   * 32 + 2*tj + 1] = __uint_as_float(h0);
        dst[(2*ti+1) * 32 + 2*tj    ] = __uint_as_float(l1);
        dst[(2*ti+1) * 32 + 2*tj + 1] = __uint_as_float(h1);
    }
}

__global__ void __launch_bounds__(256)
loss_per_b_kernel()
{
    const int b = blockIdx.x, t = threadIdx.x;
    float accl = 0.0f;
    #pragma unroll
    for (int rr = 0; rr < 4; ++rr) {
        const int ij = t + rr * 256;
        float s = 0.0f;
        for (int cc = 0; cc < NTIL; ++cc)
            s += g_gramPart[((size_t)cc * BATCH + b) * 1024 + ij];
        if (ij % 33 == 0) s -= 1.0f;
        accl = fmaf(s, s, accl);
    }
    __shared__ float red[256];
    red[t] = accl;
    __syncthreads();
    for (int o = 128; o > 0; o >>= 1) {
        if (t < o) red[t] += red[t + o];
        __syncthreads();
    }
    if (t == 0) g_lossb[b] = red[0];
}

__global__ void __launch_bounds__(256)
final_reduce_kernel(float* __restrict__ out)
{
    const int t = threadIdx.x;
    __shared__ float red[256];
    red[t] = g_lossb[t];
    __syncthreads();
    for (int o = 128; o > 0; o >>= 1) {
        if (t < o) red[t] += red[t + o];
        __syncthreads();
    }
    if (t == 0) out[0] = red[0] * (1.0f / (float)BATCH);
}

extern "C" void kernel_launch(void* const* d_in, const int* in_sizes, int n_in,
                              void* d_out, int out_size)
{
    const float* z   = (const float*)d_in[0];
    const float* W1  = (const float*)d_in[1];
    const float* b1  = (const float*)d_in[2];
    const float* W2  = (const float*)d_in[3];
    const float* b2  = (const float*)d_in[4];
    const float* lth = (const float*)d_in[5];

    pre1_kernel<<<BATCH, 256>>>(z, W1, b1);
    prepA_kernel<<<256, 256>>>(W2);

    const int smB = (DLAT * HID + HID) * sizeof(float);          // 67,584
    cudaFuncSetAttribute(prepB_kernel, cudaFuncAttributeMaxDynamicSharedMemorySize, smB);
    prepB_kernel<<<BATCH, 256, smB>>>(W1);

    const int smU = 2 * 256 * USTR * sizeof(float);              // 69,632
    cudaFuncSetAttribute(mma_main, cudaFuncAttributeMaxDynamicSharedMemorySize, smU);
    mma_main<<<dim3(NTIL, BATCH / 2), 256, smU>>>(b2, lth);

    loss_per_b_kernel<<<BATCH, 256>>>();
    final_reduce_kernel<<<1, 256>>>((float*)d_out);
}

// round 10
// speedup vs baseline: 1.9950x; 1.2057x over previous
#include <cuda_runtime.h>
#include <cstdint>

#define BATCH 256
#define DLAT  32
#define HID   512
#define GENES 4000
#define NTIL  16
#define USTR  34

__device__ uint4 g_A[2 * 256 * 32 * 32];        // [prec][gtile16][ks][lane]
__device__ uint2 g_B[2 * 256 * 32 * 5 * 32];    // [prec][b][ks][nt][lane]
__device__ float g_pre1[BATCH * HID];
__device__ float g_gramPart[(size_t)NTIL * BATCH * DLAT * DLAT];
__device__ float g_lossb[BATCH];

#define FMA2(a, x, y) asm("fma.rn.f32x2 %0, %1, %2, %0;" : "+l"(a) : "l"(x), "l"(y))
#define MMA(d, a, b) \
    asm volatile("mma.sync.aligned.m16n8k16.row.col.f32.bf16.bf16.f32 " \
        "{%0,%1,%2,%3}, {%4,%5,%6,%7}, {%8,%9}, {%0,%1,%2,%3};" \
        : "+f"((d)[0]), "+f"((d)[1]), "+f"((d)[2]), "+f"((d)[3]) \
        : "r"((a).x), "r"((a).y), "r"((a).z), "r"((a).w), "r"((b).x), "r"((b).y))

__device__ __forceinline__ unsigned f2bf(float f) {
    unsigned u = __float_as_uint(f);
    return (u + 0x7FFFu + ((u >> 16) & 1u)) >> 16;
}
__device__ __forceinline__ float bf2f(unsigned h) { return __uint_as_float(h << 16); }
__device__ __forceinline__ unsigned packbf(float a, float b, unsigned& lo) {
    const unsigned ha = f2bf(a), hb = f2bf(b);
    lo = f2bf(a - bf2f(ha)) | (f2bf(b - bf2f(hb)) << 16);
    return ha | (hb << 16);
}

// ---- prep: pre1[b][k] ----
__global__ void __launch_bounds__(256)
pre1_kernel(const float* __restrict__ z, const float* __restrict__ W1,
            const float* __restrict__ b1)
{
    __shared__ float sZ[DLAT];
    const int b = blockIdx.x, tid = threadIdx.x;
    if (tid < DLAT) sZ[tid] = z[b * DLAT + tid];
    __syncthreads();
    #pragma unroll
    for (int kk = 0; kk < 2; ++kk) {
        const int k = tid + kk * 256;
        float acc = b1[k];
        #pragma unroll
        for (int i = 0; i < DLAT; ++i) acc = fmaf(sZ[i], W1[i * HID + k], acc);
        g_pre1[b * HID + k] = acc;
    }
}

// ---- prep: A fragments from W2 (per 16-gene tile) ----
__global__ void __launch_bounds__(256)
prepA_kernel(const float* __restrict__ W2)
{
    __shared__ float sW2[HID * 16];          // [k][g-local]
    const int gt = blockIdx.x, tid = threadIdx.x;
    for (int idx = tid; idx < HID * 16; idx += 256) {
        const int k = idx >> 4, gl = idx & 15, g = gt * 16 + gl;
        sW2[idx] = (g < GENES) ? W2[k * GENES + g] : 0.0f;
    }
    __syncthreads();
    const int lane = tid & 31, ks8 = tid >> 5;
    const int r = lane >> 2, c = lane & 3;
    #pragma unroll
    for (int ko = 0; ko < 4; ++ko) {
        const int ks = ko * 8 + ks8, k0 = ks * 16 + 2 * c;
        uint4 hi, lo;
        hi.x = packbf(sW2[k0 * 16 + r],       sW2[(k0 + 1) * 16 + r],       lo.x);
        hi.y = packbf(sW2[k0 * 16 + r + 8],   sW2[(k0 + 1) * 16 + r + 8],   lo.y);
        hi.z = packbf(sW2[(k0 + 8) * 16 + r],     sW2[(k0 + 9) * 16 + r],     lo.z);
        hi.w = packbf(sW2[(k0 + 8) * 16 + r + 8], sW2[(k0 + 9) * 16 + r + 8], lo.w);
        g_A[(0 * 256 + gt) * 1024 + ks * 32 + lane] = hi;
        g_A[(1 * 256 + gt) * 1024 + ks * 32 + lane] = lo;
    }
}

// ---- prep: B fragments = (masked W1 | h) per batch ----
__global__ void __launch_bounds__(256)
prepB_kernel(const float* __restrict__ W1)
{
    extern __shared__ float sm[];
    float* sW1 = sm;                // [32][512]
    float* sP  = sm + DLAT * HID;   // [512]
    const int b = blockIdx.x, tid = threadIdx.x;
    for (int idx = tid; idx < DLAT * HID; idx += 256) sW1[idx] = W1[idx];
    for (int idx = tid; idx < HID; idx += 256) sP[idx] = g_pre1[b * HID + idx];
    __syncthreads();
    const int lane = tid & 31, ks8 = tid >> 5;
    const int r = lane >> 2, c = lane & 3;
    #pragma unroll
    for (int ko = 0; ko < 4; ++ko) {
        const int ks = ko * 8 + ks8, k0 = ks * 16 + 2 * c;
        const bool m0 = sP[k0] > 0.f, m1 = sP[k0 + 1] > 0.f;
        const bool m8 = sP[k0 + 8] > 0.f, m9 = sP[k0 + 9] > 0.f;
        #pragma unroll
        for (int nt = 0; nt < 5; ++nt) {
            float v0 = 0.f, v1 = 0.f, v8 = 0.f, v9 = 0.f;
            if (nt < 4) {
                const int n = nt * 8 + r;
                v0 = m0 ? sW1[n * HID + k0]     : 0.f;
                v1 = m1 ? sW1[n * HID + k0 + 1] : 0.f;
                v8 = m8 ? sW1[n * HID + k0 + 8] : 0.f;
                v9 = m9 ? sW1[n * HID + k0 + 9] : 0.f;
            } else if (r == 0) {                 // n = 32: h row
                v0 = fmaxf(sP[k0], 0.f);     v1 = fmaxf(sP[k0 + 1], 0.f);
                v8 = fmaxf(sP[k0 + 8], 0.f); v9 = fmaxf(sP[k0 + 9], 0.f);
            }
            uint2 hi, lo;
            hi.x = packbf(v0, v1, lo.x);
            hi.y = packbf(v8, v9, lo.y);
            const int base = ks * 160 + nt * 32 + lane;
            g_B[(0 * 256 + b) * 5120 + base] = hi;
            g_B[(1 * 256 + b) * 5120 + base] = lo;
        }
    }
}

__device__ __forceinline__ float gene_scale(float pre2, int g,
                                            const float* b2, const float* lth)
{
    if (g >= GENES) return 0.0f;
    const float x  = pre2 + __ldg(b2 + g);
    const float mu = (x > 0.f) ? (x + log1pf(__expf(-x))) : log1pf(__expf(x));
    const float sg = 1.0f / (1.0f + __expf(-x));
    const float th = __expf(__ldg(lth + g));
    return sg * sqrtf(th / fmaf(mu, mu + th, 1e-6f));
}

// ---- main: warp-level bf16 MMA (3-term), 1 batch/block, 2 blocks/SM ----
__global__ void __launch_bounds__(256, 2)
mma_main(const float* __restrict__ b2, const float* __restrict__ lth)
{
    extern __shared__ float sU[];   // [256 g][USTR]
    const int tid = threadIdx.x, w = tid >> 5, lane = tid & 31;
    const int tile = blockIdx.x, b = blockIdx.y;

    const uint4* pA[2][2];
    #pragma unroll
    for (int p = 0; p < 2; ++p)
        #pragma unroll
        for (int m = 0; m < 2; ++m)
            pA[p][m] = g_A + (p * 256 + tile * 16 + w * 2 + m) * 1024 + lane;
    const uint2* pB[2];
    #pragma unroll
    for (int p = 0; p < 2; ++p)
        pB[p] = g_B + (p * 256 + b) * 5120 + lane;

    float acc[2][5][4];
    #pragma unroll
    for (int m = 0; m < 2; ++m)
        #pragma unroll
        for (int n = 0; n < 5; ++n)
            #pragma unroll
            for (int e = 0; e < 4; ++e) acc[m][n][e] = 0.0f;

    uint4 Ab[2][2][2];              // [stage][prec][m]
    uint2 Bb[2][2][5];              // [stage][prec][n]
    #pragma unroll
    for (int p = 0; p < 2; ++p) {
        #pragma unroll
        for (int m = 0; m < 2; ++m) Ab[0][p][m] = pA[p][m][0];
        #pragma unroll
        for (int n = 0; n < 5; ++n) Bb[0][p][n] = pB[p][n * 32];
    }

    #pragma unroll 2
    for (int ks = 0; ks < 32; ++ks) {
        const int cur = ks & 1, nxt = cur ^ 1;
        const int ksn = (ks < 31) ? ks + 1 : 31;
        #pragma unroll
        for (int p = 0; p < 2; ++p) {
            #pragma unroll
            for (int m = 0; m < 2; ++m) Ab[nxt][p][m] = pA[p][m][ksn * 32];
            #pragma unroll
            for (int n = 0; n < 5; ++n)
                Bb[nxt][p][n] = pB[p][ksn * 160 + n * 32];
        }
        #pragma unroll
        for (int n = 0; n < 5; ++n)
            #pragma unroll
            for (int m = 0; m < 2; ++m) {
                MMA(acc[m][n], Ab[cur][0][m], Bb[cur][0][n]);
                MMA(acc[m][n], Ab[cur][0][m], Bb[cur][1][n]);
                MMA(acc[m][n], Ab[cur][1][m], Bb[cur][0][n]);
            }
    }

    // epilogue: pre2 from col 32 (nt=4 col 0) -> sc -> U in smem
    const int r = lane >> 2, c2 = (lane & 3) * 2;
    #pragma unroll
    for (int m = 0; m < 2; ++m) {
        const float pr  = __shfl_sync(0xFFFFFFFFu, acc[m][4][0], lane & 28);
        const float pr8 = __shfl_sync(0xFFFFFFFFu, acc[m][4][2], lane & 28);
        const int gbase = tile * 256 + w * 32 + m * 16;
        const float sc0 = gene_scale(pr,  gbase + r,     b2, lth);
        const float sc1 = gene_scale(pr8, gbase + r + 8, b2, lth);
        float* u0 = sU + (w * 32 + m * 16 + r) * USTR;
        float* u1 = u0 + 8 * USTR;
        #pragma unroll
        for (int n = 0; n < 4; ++n) {
            *reinterpret_cast<float2*>(u0 + n * 8 + c2) =
                make_float2(acc[m][n][0] * sc0, acc[m][n][1] * sc0);
            *reinterpret_cast<float2*>(u1 + n * 8 + c2) =
                make_float2(acc[m][n][2] * sc1, acc[m][n][3] * sc1);
        }
    }
    __syncthreads();

    // SYRK: Gram partial = U^T U (f32x2, 2x2 per thread) over 256 rows
    const int ti = tid & 15, tj = tid >> 4;
    {
        const float* pa = sU + 2 * ti;
        const float* pq = sU + 2 * tj;
        unsigned long long ga0 = 0ULL, ga1 = 0ULL;
        #pragma unroll 4
        for (int rI = 0; rI < 256; ++rI) {
            const unsigned long long av =
                *reinterpret_cast<const unsigned long long*>(pa + rI * USTR);
            const unsigned long long bv =
                *reinterpret_cast<const unsigned long long*>(pq + rI * USTR);
            unsigned alo, ahi;
            asm("mov.b64 {%0,%1}, %2;" : "=r"(alo), "=r"(ahi) : "l"(av));
            unsigned long long ad0, ad1;
            asm("mov.b64 %0, {%1,%1};" : "=l"(ad0) : "r"(alo));
            asm("mov.b64 %0, {%1,%1};" : "=l"(ad1) : "r"(ahi));
            FMA2(ga0, ad0, bv);
            FMA2(ga1, ad1, bv);
        }
        float* dst = g_gramPart + ((size_t)tile * BATCH + b) * 1024;
        unsigned l0, h0, l1, h1;
        asm("mov.b64 {%0,%1}, %2;" : "=r"(l0), "=r"(h0) : "l"(ga0));
        asm("mov.b64 {%0,%1}, %2;" : "=r"(l1), "=r"(h1) : "l"(ga1));
        dst[(2*ti)   * 32 + 2*tj    ] = __uint_as_float(l0);
        dst[(2*ti)   * 32 + 2*tj + 1] = __uint_as_float(h0);
        dst[(2*ti+1) * 32 + 2*tj    ] = __uint_as_float(l1);
        dst[(2*ti+1) * 32 + 2*tj + 1] = __uint_as_float(h1);
    }
}

__global__ void __launch_bounds__(256)
loss_per_b_kernel()
{
    const int b = blockIdx.x, t = threadIdx.x;
    float accl = 0.0f;
    #pragma unroll
    for (int rr = 0; rr < 4; ++rr) {
        const int ij = t + rr * 256;
        float s = 0.0f;
        for (int cc = 0; cc < NTIL; ++cc)
            s += g_gramPart[((size_t)cc * BATCH + b) * 1024 + ij];
        if (ij % 33 == 0) s -= 1.0f;
        accl = fmaf(s, s, accl);
    }
    __shared__ float red[256];
    red[t] = accl;
    __syncthreads();
    for (int o = 128; o > 0; o >>= 1) {
        if (t < o) red[t] += red[t + o];
        __syncthreads();
    }
    if (t == 0) g_lossb[b] = red[0];
}

__global__ void __launch_bounds__(256)
final_reduce_kernel(float* __restrict__ out)
{
    const int t = threadIdx.x;
    __shared__ float red[256];
    red[t] = g_lossb[t];
    __syncthreads();
    for (int o = 128; o > 0; o >>= 1) {
        if (t < o) red[t] += red[t + o];
        __syncthreads();
    }
    if (t == 0) out[0] = red[0] * (1.0f / (float)BATCH);
}

extern "C" void kernel_launch(void* const* d_in, const int* in_sizes, int n_in,
                              void* d_out, int out_size)
{
    const float* z   = (const float*)d_in[0];
    const float* W1  = (const float*)d_in[1];
    const float* b1  = (const float*)d_in[2];
    const float* W2  = (const float*)d_in[3];
    const float* b2  = (const float*)d_in[4];
    const float* lth = (const float*)d_in[5];

    pre1_kernel<<<BATCH, 256>>>(z, W1, b1);
    prepA_kernel<<<256, 256>>>(W2);

    const int smB = (DLAT * HID + HID) * sizeof(float);          // 67,584
    cudaFuncSetAttribute(prepB_kernel, cudaFuncAttributeMaxDynamicSharedMemorySize, smB);
    prepB_kernel<<<BATCH, 256, smB>>>(W1);

    const int smU = 256 * USTR * sizeof(float);                  // 34,816
    cudaFuncSetAttribute(mma_main, cudaFuncAttributeMaxDynamicSharedMemorySize, smU);
    mma_main<<<dim3(NTIL, BATCH), 256, smU>>>(b2, lth);

    loss_per_b_kernel<<<BATCH, 256>>>();
    final_reduce_kernel<<<1, 256>>>((float*)d_out);
}

// round 11
// speedup vs baseline: 2.1408x; 1.0731x over previous
#include <cuda_runtime.h>
#include <cstdint>

#define BATCH 256
#define DLAT  32
#define HID   512
#define GENES 4000
#define NTIL  16
#define USTR  34

__device__ uint4 g_A[2 * 256 * 32 * 32];        // [prec][gtile16][ks][lane]
__device__ uint2 g_B[2 * 256 * 32 * 4 * 32];    // [prec][b][ks][nt][lane]
__device__ float g_pre1[BATCH * HID];
__device__ float g_sc[BATCH * 4096];
__device__ float g_gramPart[(size_t)NTIL * BATCH * DLAT * DLAT];
__device__ float g_lossb[BATCH];

#define FMA2(a, x, y) asm("fma.rn.f32x2 %0, %1, %2, %0;" : "+l"(a) : "l"(x), "l"(y))
#define MMA(d, a, b) \
    asm volatile("mma.sync.aligned.m16n8k16.row.col.f32.bf16.bf16.f32 " \
        "{%0,%1,%2,%3}, {%4,%5,%6,%7}, {%8,%9}, {%0,%1,%2,%3};" \
        : "+f"((d)[0]), "+f"((d)[1]), "+f"((d)[2]), "+f"((d)[3]) \
        : "r"((a).x), "r"((a).y), "r"((a).z), "r"((a).w), "r"((b).x), "r"((b).y))

__device__ __forceinline__ unsigned f2bf(float f) {
    unsigned u = __float_as_uint(f);
    return (u + 0x7FFFu + ((u >> 16) & 1u)) >> 16;
}
__device__ __forceinline__ float bf2f(unsigned h) { return __uint_as_float(h << 16); }
__device__ __forceinline__ unsigned packbf(float a, float b, unsigned& lo) {
    const unsigned ha = f2bf(a), hb = f2bf(b);
    lo = f2bf(a - bf2f(ha)) | (f2bf(b - bf2f(hb)) << 16);
    return ha | (hb << 16);
}

// ---- prep: pre1[b][k] ----
__global__ void __launch_bounds__(256)
pre1_kernel(const float* __restrict__ z, const float* __restrict__ W1,
            const float* __restrict__ b1)
{
    __shared__ float sZ[DLAT];
    const int b = blockIdx.x, tid = threadIdx.x;
    if (tid < DLAT) sZ[tid] = z[b * DLAT + tid];
    __syncthreads();
    #pragma unroll
    for (int kk = 0; kk < 2; ++kk) {
        const int k = tid + kk * 256;
        float acc = b1[k];
        #pragma unroll
        for (int i = 0; i < DLAT; ++i) acc = fmaf(sZ[i], W1[i * HID + k], acc);
        g_pre1[b * HID + k] = acc;
    }
}

// ---- prep: A fragments from W2 ----
__global__ void __launch_bounds__(256)
prepA_kernel(const float* __restrict__ W2)
{
    __shared__ float sW2[HID * 16];
    const int gt = blockIdx.x, tid = threadIdx.x;
    for (int idx = tid; idx < HID * 16; idx += 256) {
        const int k = idx >> 4, gl = idx & 15, g = gt * 16 + gl;
        sW2[idx] = (g < GENES) ? W2[k * GENES + g] : 0.0f;
    }
    __syncthreads();
    const int lane = tid & 31, ks8 = tid >> 5;
    const int r = lane >> 2, c = lane & 3;
    #pragma unroll
    for (int ko = 0; ko < 4; ++ko) {
        const int ks = ko * 8 + ks8, k0 = ks * 16 + 2 * c;
        uint4 hi, lo;
        hi.x = packbf(sW2[k0 * 16 + r],       sW2[(k0 + 1) * 16 + r],       lo.x);
        hi.y = packbf(sW2[k0 * 16 + r + 8],   sW2[(k0 + 1) * 16 + r + 8],   lo.y);
        hi.z = packbf(sW2[(k0 + 8) * 16 + r],     sW2[(k0 + 9) * 16 + r],     lo.z);
        hi.w = packbf(sW2[(k0 + 8) * 16 + r + 8], sW2[(k0 + 9) * 16 + r + 8], lo.w);
        g_A[(0 * 256 + gt) * 1024 + ks * 32 + lane] = hi;
        g_A[(1 * 256 + gt) * 1024 + ks * 32 + lane] = lo;
    }
}

// ---- prep: B fragments = masked W1 (32 cols only) ----
__global__ void __launch_bounds__(256)
prepB_kernel(const float* __restrict__ W1)
{
    extern __shared__ float sm[];
    float* sW1 = sm;                // [32][512]
    float* sP  = sm + DLAT * HID;   // [512]
    const int b = blockIdx.x, tid = threadIdx.x;
    for (int idx = tid; idx < DLAT * HID; idx += 256) sW1[idx] = W1[idx];
    for (int idx = tid; idx < HID; idx += 256) sP[idx] = g_pre1[b * HID + idx];
    __syncthreads();
    const int lane = tid & 31, ks8 = tid >> 5;
    const int r = lane >> 2, c = lane & 3;
    #pragma unroll
    for (int ko = 0; ko < 4; ++ko) {
        const int ks = ko * 8 + ks8, k0 = ks * 16 + 2 * c;
        const bool m0 = sP[k0] > 0.f, m1 = sP[k0 + 1] > 0.f;
        const bool m8 = sP[k0 + 8] > 0.f, m9 = sP[k0 + 9] > 0.f;
        #pragma unroll
        for (int nt = 0; nt < 4; ++nt) {
            const int n = nt * 8 + r;
            const float v0 = m0 ? sW1[n * HID + k0]     : 0.f;
            const float v1 = m1 ? sW1[n * HID + k0 + 1] : 0.f;
            const float v8 = m8 ? sW1[n * HID + k0 + 8] : 0.f;
            const float v9 = m9 ? sW1[n * HID + k0 + 9] : 0.f;
            uint2 hi, lo;
            hi.x = packbf(v0, v1, lo.x);
            hi.y = packbf(v8, v9, lo.y);
            const int base = ks * 128 + nt * 32 + lane;
            g_B[(0 * 256 + b) * 4096 + base] = hi;
            g_B[(1 * 256 + b) * 4096 + base] = lo;
        }
    }
}

// ---- prep: sc[b][g] = sigma * sqrt(theta / (mu*(mu+theta)+eps)), fp32 pre2 ----
__global__ void __launch_bounds__(256)
sc_kernel(const float* __restrict__ W2, const float* __restrict__ b2,
          const float* __restrict__ lth)
{
    __shared__ float sh[HID * 16];           // [k][bb] relu(pre1), 16 batches
    const int gc = blockIdx.x, bg = blockIdx.y, tid = threadIdx.x;
    for (int x = tid; x < 16 * HID; x += 256) {
        const int bb = x >> 9, k = x & 511;
        sh[k * 16 + bb] = fmaxf(g_pre1[(bg * 16 + bb) * HID + k], 0.0f);
    }
    __syncthreads();
    const int g = gc * 256 + tid;
    const bool gok = (g < GENES);
    unsigned long long acc2[8];
    #pragma unroll
    for (int j = 0; j < 8; ++j) acc2[j] = 0ULL;
    #pragma unroll 4
    for (int k = 0; k < HID; ++k) {
        const float w = gok ? __ldg(W2 + k * GENES + g) : 0.0f;
        unsigned long long ws;
        asm("mov.b64 %0, {%1,%1};" : "=l"(ws) : "r"(__float_as_uint(w)));
        const ulonglong2* hp = reinterpret_cast<const ulonglong2*>(sh + k * 16);
        #pragma unroll
        for (int j = 0; j < 4; ++j) {
            const ulonglong2 h2 = hp[j];
            FMA2(acc2[2*j],     ws, h2.x);
            FMA2(acc2[2*j + 1], ws, h2.y);
        }
    }
    const float bb2 = gok ? __ldg(b2 + g) : 0.0f;
    const float th  = gok ? __expf(__ldg(lth + g)) : 1.0f;
    #pragma unroll
    for (int j = 0; j < 8; ++j) {
        unsigned lo, hi;
        asm("mov.b64 {%0,%1}, %2;" : "=r"(lo), "=r"(hi) : "l"(acc2[j]));
        #pragma unroll
        for (int e = 0; e < 2; ++e) {
            const float x = (e ? __uint_as_float(hi) : __uint_as_float(lo)) + bb2;
            const float mu = (x > 0.f) ? (x + log1pf(__expf(-x))) : log1pf(__expf(x));
            const float sg = 1.0f / (1.0f + __expf(-x));
            const float sc = gok ? sg * sqrtf(th / fmaf(mu, mu + th, 1e-6f)) : 0.0f;
            g_sc[(bg * 16 + 2 * j + e) * 4096 + g] = sc;
        }
    }
}

// ---- main: warp bf16 MMA (3-term), n=32 cols, sc precomputed ----
__global__ void __launch_bounds__(256, 2)
mma_main()
{
    extern __shared__ float sU[];   // [256 g][USTR]
    const int tid = threadIdx.x, w = tid >> 5, lane = tid & 31;
    const int b = blockIdx.x, tile = blockIdx.y;

    const uint4* pA[2][2];
    #pragma unroll
    for (int p = 0; p < 2; ++p)
        #pragma unroll
        for (int m = 0; m < 2; ++m)
            pA[p][m] = g_A + (p * 256 + tile * 16 + w * 2 + m) * 1024 + lane;
    const uint2* pB[2];
    #pragma unroll
    for (int p = 0; p < 2; ++p) pB[p] = g_B + (p * 256 + b) * 4096 + lane;

    float acc[2][4][4];
    #pragma unroll
    for (int m = 0; m < 2; ++m)
        #pragma unroll
        for (int n = 0; n < 4; ++n)
            #pragma unroll
            for (int e = 0; e < 4; ++e) acc[m][n][e] = 0.0f;

    uint4 Ab[2][2][2];              // [stage][prec][m]
    uint2 Bb[2][2][4];              // [stage][prec][n]
    #pragma unroll
    for (int p = 0; p < 2; ++p) {
        #pragma unroll
        for (int m = 0; m < 2; ++m) Ab[0][p][m] = pA[p][m][0];
        #pragma unroll
        for (int n = 0; n < 4; ++n) Bb[0][p][n] = pB[p][n * 32];
    }

    #pragma unroll 8
    for (int ks = 0; ks < 32; ++ks) {
        const int cur = ks & 1, nxt = cur ^ 1;
        const int ksn = (ks < 31) ? ks + 1 : 31;
        #pragma unroll
        for (int p = 0; p < 2; ++p) {
            #pragma unroll
            for (int m = 0; m < 2; ++m) Ab[nxt][p][m] = pA[p][m][ksn * 32];
            #pragma unroll
            for (int n = 0; n < 4; ++n)
                Bb[nxt][p][n] = pB[p][ksn * 128 + n * 32];
        }
        #pragma unroll
        for (int n = 0; n < 4; ++n)
            #pragma unroll
            for (int m = 0; m < 2; ++m) {
                MMA(acc[m][n], Ab[cur][0][m], Bb[cur][0][n]);
                MMA(acc[m][n], Ab[cur][0][m], Bb[cur][1][n]);
                MMA(acc[m][n], Ab[cur][1][m], Bb[cur][0][n]);
            }
    }

    // epilogue: U = sc * V into smem
    const int r = lane >> 2, c2 = (lane & 3) * 2;
    const float* scb = g_sc + b * 4096 + tile * 256 + w * 32;
    #pragma unroll
    for (int m = 0; m < 2; ++m) {
        const float sc0 = __ldg(scb + m * 16 + r);
        const float sc1 = __ldg(scb + m * 16 + r + 8);
        float* u0 = sU + (w * 32 + m * 16 + r) * USTR;
        float* u1 = u0 + 8 * USTR;
        #pragma unroll
        for (int n = 0; n < 4; ++n) {
            *reinterpret_cast<float2*>(u0 + n * 8 + c2) =
                make_float2(acc[m][n][0] * sc0, acc[m][n][1] * sc0);
            *reinterpret_cast<float2*>(u1 + n * 8 + c2) =
                make_float2(acc[m][n][2] * sc1, acc[m][n][3] * sc1);
        }
    }
    __syncthreads();

    // SYRK: Gram partial = U^T U
    const int ti = tid & 15, tj = tid >> 4;
    {
        const float* pa = sU + 2 * ti;
        const float* pq = sU + 2 * tj;
        unsigned long long ga0 = 0ULL, ga1 = 0ULL;
        #pragma unroll 4
        for (int rI = 0; rI < 256; ++rI) {
            const unsigned long long av =
                *reinterpret_cast<const unsigned long long*>(pa + rI * USTR);
            const unsigned long long bv =
                *reinterpret_cast<const unsigned long long*>(pq + rI * USTR);
            unsigned alo, ahi;
            asm("mov.b64 {%0,%1}, %2;" : "=r"(alo), "=r"(ahi) : "l"(av));
            unsigned long long ad0, ad1;
            asm("mov.b64 %0, {%1,%1};" : "=l"(ad0) : "r"(alo));
            asm("mov.b64 %0, {%1,%1};" : "=l"(ad1) : "r"(ahi));
            FMA2(ga0, ad0, bv);
            FMA2(ga1, ad1, bv);
        }
        float* dst = g_gramPart + ((size_t)tile * BATCH + b) * 1024;
        unsigned l0, h0, l1, h1;
        asm("mov.b64 {%0,%1}, %2;" : "=r"(l0), "=r"(h0) : "l"(ga0));
        asm("mov.b64 {%0,%1}, %2;" : "=r"(l1), "=r"(h1) : "l"(ga1));
        dst[(2*ti)   * 32 + 2*tj    ] = __uint_as_float(l0);
        dst[(2*ti)   * 32 + 2*tj + 1] = __uint_as_float(h0);
        dst[(2*ti+1) * 32 + 2*tj    ] = __uint_as_float(l1);
        dst[(2*ti+1) * 32 + 2*tj + 1] = __uint_as_float(h1);
    }
}

__global__ void __launch_bounds__(256)
loss_per_b_kernel()
{
    const int b = blockIdx.x, t = threadIdx.x;
    float accl = 0.0f;
    #pragma unroll
    for (int rr = 0; rr < 4; ++rr) {
        const int ij = t + rr * 256;
        float s = 0.0f;
        for (int cc = 0; cc < NTIL; ++cc)
            s += g_gramPart[((size_t)cc * BATCH + b) * 1024 + ij];
        if (ij % 33 == 0) s -= 1.0f;
        accl = fmaf(s, s, accl);
    }
    __shared__ float red[256];
    red[t] = accl;
    __syncthreads();
    for (int o = 128; o > 0; o >>= 1) {
        if (t < o) red[t] += red[t + o];
        __syncthreads();
    }
    if (t == 0) g_lossb[b] = red[0];
}

__global__ void __launch_bounds__(256)
final_reduce_kernel(float* __restrict__ out)
{
    const int t = threadIdx.x;
    __shared__ float red[256];
    red[t] = g_lossb[t];
    __syncthreads();
    for (int o = 128; o > 0; o >>= 1) {
        if (t < o) red[t] += red[t + o];
        __syncthreads();
    }
    if (t == 0) out[0] = red[0] * (1.0f / (float)BATCH);
}

extern "C" void kernel_launch(void* const* d_in, const int* in_sizes, int n_in,
                              void* d_out, int out_size)
{
    const float* z   = (const float*)d_in[0];
    const float* W1  = (const float*)d_in[1];
    const float* b1  = (const float*)d_in[2];
    const float* W2  = (const float*)d_in[3];
    const float* b2  = (const float*)d_in[4];
    const float* lth = (const float*)d_in[5];

    pre1_kernel<<<BATCH, 256>>>(z, W1, b1);
    prepA_kernel<<<256, 256>>>(W2);

    const int smB = (DLAT * HID + HID) * sizeof(float);
    cudaFuncSetAttribute(prepB_kernel, cudaFuncAttributeMaxDynamicSharedMemorySize, smB);
    prepB_kernel<<<BATCH, 256, smB>>>(W1);
    sc_kernel<<<dim3(16, 16), 256>>>(W2, b2, lth);

    const int smU = 256 * USTR * sizeof(float);
    cudaFuncSetAttribute(mma_main, cudaFuncAttributeMaxDynamicSharedMemorySize, smU);
    mma_main<<<dim3(BATCH, NTIL), 256, smU>>>();

    loss_per_b_kernel<<<BATCH, 256>>>();
    final_reduce_kernel<<<1, 256>>>((float*)d_out);
}

// round 12
// speedup vs baseline: 2.2623x; 1.0568x over previous
#include <cuda_runtime.h>
#include <cstdint>

#define BATCH 256
#define DLAT  32
#define HID   512
#define GENES 4000
#define NTIL  16
#define USTR  34

__device__ uint4 g_A[2 * 256 * 32 * 32];        // [prec][gtile16][ks][lane]
__device__ uint2 g_B[2 * 256 * 32 * 4 * 32];    // [prec][b][ks][nt][lane]
__device__ uint2 g_Bh[2 * 32 * 32 * 32];        // [prec][btile8][ks][lane]
__device__ float g_pre1[BATCH * HID];
__device__ float g_sc[BATCH * 4096];
__device__ float g_gramPart[(size_t)NTIL * BATCH * DLAT * DLAT];
__device__ float g_lossb[BATCH];

#define FMA2(a, x, y) asm("fma.rn.f32x2 %0, %1, %2, %0;" : "+l"(a) : "l"(x), "l"(y))
#define MMA(d, a, b) \
    asm volatile("mma.sync.aligned.m16n8k16.row.col.f32.bf16.bf16.f32 " \
        "{%0,%1,%2,%3}, {%4,%5,%6,%7}, {%8,%9}, {%0,%1,%2,%3};" \
        : "+f"((d)[0]), "+f"((d)[1]), "+f"((d)[2]), "+f"((d)[3]) \
        : "r"((a).x), "r"((a).y), "r"((a).z), "r"((a).w), "r"((b).x), "r"((b).y))

__device__ __forceinline__ unsigned f2bf(float f) {
    unsigned u = __float_as_uint(f);
    return (u + 0x7FFFu + ((u >> 16) & 1u)) >> 16;
}
__device__ __forceinline__ float bf2f(unsigned h) { return __uint_as_float(h << 16); }
__device__ __forceinline__ unsigned packbf(float a, float b, unsigned& lo) {
    const unsigned ha = f2bf(a), hb = f2bf(b);
    lo = f2bf(a - bf2f(ha)) | (f2bf(b - bf2f(hb)) << 16);
    return ha | (hb << 16);
}

// ---- prep: pre1[b][k] ----
__global__ void __launch_bounds__(256)
pre1_kernel(const float* __restrict__ z, const float* __restrict__ W1,
            const float* __restrict__ b1)
{
    __shared__ float sZ[DLAT];
    const int b = blockIdx.x, tid = threadIdx.x;
    if (tid < DLAT) sZ[tid] = z[b * DLAT + tid];
    __syncthreads();
    #pragma unroll
    for (int kk = 0; kk < 2; ++kk) {
        const int k = tid + kk * 256;
        float acc = b1[k];
        #pragma unroll
        for (int i = 0; i < DLAT; ++i) acc = fmaf(sZ[i], W1[i * HID + k], acc);
        g_pre1[b * HID + k] = acc;
    }
}

// ---- prep: A fragments from W2 ----
__global__ void __launch_bounds__(256)
prepA_kernel(const float* __restrict__ W2)
{
    __shared__ float sW2[HID * 16];
    const int gt = blockIdx.x, tid = threadIdx.x;
    for (int idx = tid; idx < HID * 16; idx += 256) {
        const int k = idx >> 4, gl = idx & 15, g = gt * 16 + gl;
        sW2[idx] = (g < GENES) ? W2[k * GENES + g] : 0.0f;
    }
    __syncthreads();
    const int lane = tid & 31, ks8 = tid >> 5;
    const int r = lane >> 2, c = lane & 3;
    #pragma unroll
    for (int ko = 0; ko < 4; ++ko) {
        const int ks = ko * 8 + ks8, k0 = ks * 16 + 2 * c;
        uint4 hi, lo;
        hi.x = packbf(sW2[k0 * 16 + r],       sW2[(k0 + 1) * 16 + r],       lo.x);
        hi.y = packbf(sW2[k0 * 16 + r + 8],   sW2[(k0 + 1) * 16 + r + 8],   lo.y);
        hi.z = packbf(sW2[(k0 + 8) * 16 + r],     sW2[(k0 + 9) * 16 + r],     lo.z);
        hi.w = packbf(sW2[(k0 + 8) * 16 + r + 8], sW2[(k0 + 9) * 16 + r + 8], lo.w);
        g_A[(0 * 256 + gt) * 1024 + ks * 32 + lane] = hi;
        g_A[(1 * 256 + gt) * 1024 + ks * 32 + lane] = lo;
    }
}

// ---- prep: B fragments = masked W1 ----
__global__ void __launch_bounds__(256)
prepB_kernel(const float* __restrict__ W1)
{
    extern __shared__ float sm[];
    float* sW1 = sm;
    float* sP  = sm + DLAT * HID;
    const int b = blockIdx.x, tid = threadIdx.x;
    for (int idx = tid; idx < DLAT * HID; idx += 256) sW1[idx] = W1[idx];
    for (int idx = tid; idx < HID; idx += 256) sP[idx] = g_pre1[b * HID + idx];
    __syncthreads();
    const int lane = tid & 31, ks8 = tid >> 5;
    const int r = lane >> 2, c = lane & 3;
    #pragma unroll
    for (int ko = 0; ko < 4; ++ko) {
        const int ks = ko * 8 + ks8, k0 = ks * 16 + 2 * c;
        const bool m0 = sP[k0] > 0.f, m1 = sP[k0 + 1] > 0.f;
        const bool m8 = sP[k0 + 8] > 0.f, m9 = sP[k0 + 9] > 0.f;
        #pragma unroll
        for (int nt = 0; nt < 4; ++nt) {
            const int n = nt * 8 + r;
            const float v0 = m0 ? sW1[n * HID + k0]     : 0.f;
            const float v1 = m1 ? sW1[n * HID + k0 + 1] : 0.f;
            const float v8 = m8 ? sW1[n * HID + k0 + 8] : 0.f;
            const float v9 = m9 ? sW1[n * HID + k0 + 9] : 0.f;
            uint2 hi, lo;
            hi.x = packbf(v0, v1, lo.x);
            hi.y = packbf(v8, v9, lo.y);
            const int base = ks * 128 + nt * 32 + lane;
            g_B[(0 * 256 + b) * 4096 + base] = hi;
            g_B[(1 * 256 + b) * 4096 + base] = lo;
        }
    }
}

// ---- prep: h fragments (batches on n-axis) ----
__global__ void __launch_bounds__(256)
prepH_kernel()
{
    __shared__ float sh[8 * HID];
    const int bt = blockIdx.x, tid = threadIdx.x;
    for (int idx = tid; idx < 8 * HID; idx += 256) {
        const int bb = idx >> 9, k = idx & 511;
        sh[bb * HID + k] = fmaxf(g_pre1[(bt * 8 + bb) * HID + k], 0.0f);
    }
    __syncthreads();
    const int lane = tid & 31, ks8 = tid >> 5;
    const int r = lane >> 2, c = lane & 3;
    #pragma unroll
    for (int ko = 0; ko < 4; ++ko) {
        const int ks = ko * 8 + ks8, k0 = ks * 16 + 2 * c;
        uint2 hi, lo;
        hi.x = packbf(sh[r * HID + k0],     sh[r * HID + k0 + 1], lo.x);
        hi.y = packbf(sh[r * HID + k0 + 8], sh[r * HID + k0 + 9], lo.y);
        g_Bh[(0 * 32 + bt) * 1024 + ks * 32 + lane] = hi;
        g_Bh[(1 * 32 + bt) * 1024 + ks * 32 + lane] = lo;
    }
}

__device__ __forceinline__ float sc_from(float x, float th) {
    const float mu = (x > 0.f) ? (x + log1pf(__expf(-x))) : log1pf(__expf(x));
    const float sg = 1.0f / (1.0f + __expf(-x));
    return sg * sqrtf(th / fmaf(mu, mu + th, 1e-6f));
}

// ---- sc via MMA: pre2[g, 32 batches] then fused weight epilogue ----
__global__ void __launch_bounds__(256)
sc_mma_kernel(const float* __restrict__ b2, const float* __restrict__ lth)
{
    const int tid = threadIdx.x, w = tid >> 5, lane = tid & 31;
    const int gt = blockIdx.x, bg = blockIdx.y;

    const uint4* pA[2][2];
    #pragma unroll
    for (int p = 0; p < 2; ++p)
        #pragma unroll
        for (int m = 0; m < 2; ++m)
            pA[p][m] = g_A + (p * 256 + gt * 16 + w * 2 + m) * 1024 + lane;
    const uint2* pH[2][4];
    #pragma unroll
    for (int p = 0; p < 2; ++p)
        #pragma unroll
        for (int n = 0; n < 4; ++n)
            pH[p][n] = g_Bh + (p * 32 + bg * 4 + n) * 1024 + lane;

    float acc[2][4][4];
    #pragma unroll
    for (int m = 0; m < 2; ++m)
        #pragma unroll
        for (int n = 0; n < 4; ++n)
            #pragma unroll
            for (int e = 0; e < 4; ++e) acc[m][n][e] = 0.0f;

    #pragma unroll 4
    for (int ks = 0; ks < 32; ++ks) {
        uint4 Ab[2][2];
        uint2 Hb[2][4];
        #pragma unroll
        for (int p = 0; p < 2; ++p) {
            #pragma unroll
            for (int m = 0; m < 2; ++m) Ab[p][m] = pA[p][m][ks * 32];
            #pragma unroll
            for (int n = 0; n < 4; ++n) Hb[p][n] = pH[p][n][ks * 32];
        }
        #pragma unroll
        for (int n = 0; n < 4; ++n)
            #pragma unroll
            for (int m = 0; m < 2; ++m) {
                MMA(acc[m][n], Ab[0][m], Hb[0][n]);
                MMA(acc[m][n], Ab[0][m], Hb[1][n]);
                MMA(acc[m][n], Ab[1][m], Hb[0][n]);
            }
    }

    const int r = lane >> 2, c = lane & 3;
    #pragma unroll
    for (int m = 0; m < 2; ++m) {
        const int g0 = gt * 256 + w * 32 + m * 16 + r;
        #pragma unroll
        for (int e2 = 0; e2 < 2; ++e2) {           // row r / row r+8
            const int g = g0 + e2 * 8;
            const bool gok = (g < GENES);
            const float bb2 = gok ? __ldg(b2 + g) : 0.0f;
            const float th  = gok ? __expf(__ldg(lth + g)) : 1.0f;
            #pragma unroll
            for (int n = 0; n < 4; ++n) {
                #pragma unroll
                for (int e1 = 0; e1 < 2; ++e1) {   // col 2c / 2c+1
                    const int bb = bg * 32 + n * 8 + 2 * c + e1;
                    const float x = acc[m][n][e2 * 2 + e1] + bb2;
                    g_sc[bb * 4096 + g] = gok ? sc_from(x, th) : 0.0f;
                }
            }
        }
    }
}

// ---- main: warp bf16 MMA (3-term), n=32, sc precomputed ----
__global__ void __launch_bounds__(256, 2)
mma_main()
{
    extern __shared__ float sU[];
    const int tid = threadIdx.x, w = tid >> 5, lane = tid & 31;
    const int b = blockIdx.x, tile = blockIdx.y;

    const uint4* pA[2][2];
    #pragma unroll
    for (int p = 0; p < 2; ++p)
        #pragma unroll
        for (int m = 0; m < 2; ++m)
            pA[p][m] = g_A + (p * 256 + tile * 16 + w * 2 + m) * 1024 + lane;
    const uint2* pB[2];
    #pragma unroll
    for (int p = 0; p < 2; ++p) pB[p] = g_B + (p * 256 + b) * 4096 + lane;

    float acc[2][4][4];
    #pragma unroll
    for (int m = 0; m < 2; ++m)
        #pragma unroll
        for (int n = 0; n < 4; ++n)
            #pragma unroll
            for (int e = 0; e < 4; ++e) acc[m][n][e] = 0.0f;

    uint4 Ab[2][2][2];
    uint2 Bb[2][2][4];
    #pragma unroll
    for (int p = 0; p < 2; ++p) {
        #pragma unroll
        for (int m = 0; m < 2; ++m) Ab[0][p][m] = pA[p][m][0];
        #pragma unroll
        for (int n = 0; n < 4; ++n) Bb[0][p][n] = pB[p][n * 32];
    }

    #pragma unroll 8
    for (int ks = 0; ks < 32; ++ks) {
        const int cur = ks & 1, nxt = cur ^ 1;
        const int ksn = (ks < 31) ? ks + 1 : 31;
        #pragma unroll
        for (int p = 0; p < 2; ++p) {
            #pragma unroll
            for (int m = 0; m < 2; ++m) Ab[nxt][p][m] = pA[p][m][ksn * 32];
            #pragma unroll
            for (int n = 0; n < 4; ++n)
                Bb[nxt][p][n] = pB[p][ksn * 128 + n * 32];
        }
        #pragma unroll
        for (int n = 0; n < 4; ++n)
            #pragma unroll
            for (int m = 0; m < 2; ++m) {
                MMA(acc[m][n], Ab[cur][0][m], Bb[cur][0][n]);
                MMA(acc[m][n], Ab[cur][0][m], Bb[cur][1][n]);
                MMA(acc[m][n], Ab[cur][1][m], Bb[cur][0][n]);
            }
    }

    // epilogue: U = sc * V into smem
    const int r = lane >> 2, c2 = (lane & 3) * 2;
    const float* scb = g_sc + b * 4096 + tile * 256 + w * 32;
    #pragma unroll
    for (int m = 0; m < 2; ++m) {
        const float sc0 = __ldg(scb + m * 16 + r);
        const float sc1 = __ldg(scb + m * 16 + r + 8);
        float* u0 = sU + (w * 32 + m * 16 + r) * USTR;
        float* u1 = u0 + 8 * USTR;
        #pragma unroll
        for (int n = 0; n < 4; ++n) {
            *reinterpret_cast<float2*>(u0 + n * 8 + c2) =
                make_float2(acc[m][n][0] * sc0, acc[m][n][1] * sc0);
            *reinterpret_cast<float2*>(u1 + n * 8 + c2) =
                make_float2(acc[m][n][2] * sc1, acc[m][n][3] * sc1);
        }
    }
    __syncthreads();

    // SYRK: Gram partial = U^T U
    const int ti = tid & 15, tj = tid >> 4;
    {
        const float* pa = sU + 2 * ti;
        const float* pq = sU + 2 * tj;
        unsigned long long ga0 = 0ULL, ga1 = 0ULL;
        #pragma unroll 4
        for (int rI = 0; rI < 256; ++rI) {
            const unsigned long long av =
                *reinterpret_cast<const unsigned long long*>(pa + rI * USTR);
            const unsigned long long bv =
                *reinterpret_cast<const unsigned long long*>(pq + rI * USTR);
            unsigned alo, ahi;
            asm("mov.b64 {%0,%1}, %2;" : "=r"(alo), "=r"(ahi) : "l"(av));
            unsigned long long ad0, ad1;
            asm("mov.b64 %0, {%1,%1};" : "=l"(ad0) : "r"(alo));
            asm("mov.b64 %0, {%1,%1};" : "=l"(ad1) : "r"(ahi));
            FMA2(ga0, ad0, bv);
            FMA2(ga1, ad1, bv);
        }
        float* dst = g_gramPart + ((size_t)tile * BATCH + b) * 1024;
        unsigned l0, h0, l1, h1;
        asm("mov.b64 {%0,%1}, %2;" : "=r"(l0), "=r"(h0) : "l"(ga0));
        asm("mov.b64 {%0,%1}, %2;" : "=r"(l1), "=r"(h1) : "l"(ga1));
        dst[(2*ti)   * 32 + 2*tj    ] = __uint_as_float(l0);
        dst[(2*ti)   * 32 + 2*tj + 1] = __uint_as_float(h0);
        dst[(2*ti+1) * 32 + 2*tj    ] = __uint_as_float(l1);
        dst[(2*ti+1) * 32 + 2*tj + 1] = __uint_as_float(h1);
    }
}

__global__ void __launch_bounds__(256)
loss_per_b_kernel()
{
    const int b = blockIdx.x, t = threadIdx.x;
    float accl = 0.0f;
    #pragma unroll
    for (int rr = 0; rr < 4; ++rr) {
        const int ij = t + rr * 256;
        float s = 0.0f;
        for (int cc = 0; cc < NTIL; ++cc)
            s += g_gramPart[((size_t)cc * BATCH + b) * 1024 + ij];
        if (ij % 33 == 0) s -= 1.0f;
        accl = fmaf(s, s, accl);
    }
    __shared__ float red[256];
    red[t] = accl;
    __syncthreads();
    for (int o = 128; o > 0; o >>= 1) {
        if (t < o) red[t] += red[t + o];
        __syncthreads();
    }
    if (t == 0) g_lossb[b] = red[0];
}

__global__ void __launch_bounds__(256)
final_reduce_kernel(float* __restrict__ out)
{
    const int t = threadIdx.x;
    __shared__ float red[256];
    red[t] = g_lossb[t];
    __syncthreads();
    for (int o = 128; o > 0; o >>= 1) {
        if (t < o) red[t] += red[t + o];
        __syncthreads();
    }
    if (t == 0) out[0] = red[0] * (1.0f / (float)BATCH);
}

extern "C" void kernel_launch(void* const* d_in, const int* in_sizes, int n_in,
                              void* d_out, int out_size)
{
    const float* z   = (const float*)d_in[0];
    const float* W1  = (const float*)d_in[1];
    const float* b1  = (const float*)d_in[2];
    const float* W2  = (const float*)d_in[3];
    const float* b2  = (const float*)d_in[4];
    const float* lth = (const float*)d_in[5];

    pre1_kernel<<<BATCH, 256>>>(z, W1, b1);
    prepA_kernel<<<256, 256>>>(W2);

    const int smB = (DLAT * HID + HID) * sizeof(float);
    cudaFuncSetAttribute(prepB_kernel, cudaFuncAttributeMaxDynamicSharedMemorySize, smB);
    prepB_kernel<<<BATCH, 256, smB>>>(W1);
    prepH_kernel<<<32, 256>>>();
    sc_mma_kernel<<<dim3(16, 8), 256>>>(b2, lth);

    const int smU = 256 * USTR * sizeof(float);
    cudaFuncSetAttribute(mma_main, cudaFuncAttributeMaxDynamicSharedMemorySize, smU);
    mma_main<<<dim3(BATCH, NTIL), 256, smU>>>();

    loss_per_b_kernel<<<BATCH, 256>>>();
    final_reduce_kernel<<<1, 256>>>((float*)d_out);
}